// round 5
// baseline (speedup 1.0000x reference)
#include <cuda_runtime.h>
#include <cstdint>

#define T_STEPS 512
#define BATCH   128
#define DIM     512
#define M_ROWS  (T_STEPS * BATCH)   // 65536

typedef unsigned long long u64;

// Scratch
__device__ float g_xproj[(size_t)T_STEPS * BATCH * DIM];  // 134 MB
__device__ float g_h[2][BATCH * DIM];                     // h exchange, [b][d]

// ---------------------------------------------------------------------------
// packed f32x2 helpers (sm_103a FFMA2 only reachable via PTX)
// ---------------------------------------------------------------------------
__device__ __forceinline__ u64 pack2(float lo, float hi) {
    u64 r;
    asm("mov.b64 %0, {%1, %2};" : "=l"(r) : "f"(lo), "f"(hi));
    return r;
}
__device__ __forceinline__ void unpack2(u64 v, float& lo, float& hi) {
    asm("mov.b64 {%0, %1}, %2;" : "=f"(lo), "=f"(hi) : "l"(v));
}
__device__ __forceinline__ u64 ffma2(u64 a, u64 b, u64 c) {
    u64 d;
    asm("fma.rn.f32x2 %0, %1, %2, %3;" : "=l"(d) : "l"(a), "l"(b), "l"(c));
    return d;
}
__device__ __forceinline__ u64 fadd2(u64 a, u64 b) {
    u64 d;
    asm("add.rn.f32x2 %0, %1, %2;" : "=l"(d) : "l"(a), "l"(b));
    return d;
}

// ============================================================================
// Kernel 1: Xproj = X @ W_in^T. FFMA2 with PRE-DUPLICATED A pairs in SMEM.
// 128x128 tile, BK=16, 256 threads, 8x8 micro, acc packed over n-pairs.
// ============================================================================
#define GEMM_A_ROW 130   // u64 per k-row (128 + 2 pad)
#define GEMM_B_ROW 132   // floats per k-row
#define GEMM_SMEM  (2*16*GEMM_A_ROW*8 + 2*16*GEMM_B_ROW*4)   // 50176 B

__global__ void __launch_bounds__(256, 2)
xproj_gemm(const float* __restrict__ A, const float* __restrict__ W) {
    extern __shared__ __align__(16) char gsm[];
    u64*   As2 = (u64*)gsm;                                // [2][16][130] dup
    float* Bs  = (float*)(gsm + 2 * 16 * GEMM_A_ROW * 8);  // [2][16][132]

    const int tid = threadIdx.x;
    const int tx = tid & 15;
    const int ty = tid >> 4;
    const int m0 = blockIdx.y * 128;
    const int n0 = blockIdx.x * 128;

    u64 acc2[8][4];
#pragma unroll
    for (int i = 0; i < 8; i++)
#pragma unroll
        for (int j = 0; j < 4; j++) acc2[i][j] = 0ull;

    float4 ra[2], rb[2];

#pragma unroll
    for (int j = 0; j < 2; j++) {
        int i  = tid + j * 256;
        int rr = i >> 2;
        int kk = (i & 3) << 2;
        ra[j] = *(const float4*)(A + (size_t)(m0 + rr) * 512 + kk);
        rb[j] = *(const float4*)(W + (size_t)(n0 + rr) * 512 + kk);
    }
#pragma unroll
    for (int j = 0; j < 2; j++) {
        int i  = tid + j * 256;
        int rr = i >> 2;
        int kk = (i & 3) << 2;
        u64* ad = As2 + (size_t)kk * GEMM_A_ROW + rr;
        ad[0 * GEMM_A_ROW] = pack2(ra[j].x, ra[j].x);
        ad[1 * GEMM_A_ROW] = pack2(ra[j].y, ra[j].y);
        ad[2 * GEMM_A_ROW] = pack2(ra[j].z, ra[j].z);
        ad[3 * GEMM_A_ROW] = pack2(ra[j].w, ra[j].w);
        float* bd = Bs + (size_t)kk * GEMM_B_ROW + rr;
        bd[0 * GEMM_B_ROW] = rb[j].x;
        bd[1 * GEMM_B_ROW] = rb[j].y;
        bd[2 * GEMM_B_ROW] = rb[j].z;
        bd[3 * GEMM_B_ROW] = rb[j].w;
    }
    __syncthreads();

    for (int s = 0; s < 32; s++) {
        const int cb = s & 1;
        if (s < 31) {
            const int kc = (s + 1) * 16;
#pragma unroll
            for (int j = 0; j < 2; j++) {
                int i  = tid + j * 256;
                int rr = i >> 2;
                int kk = (i & 3) << 2;
                ra[j] = *(const float4*)(A + (size_t)(m0 + rr) * 512 + kc + kk);
                rb[j] = *(const float4*)(W + (size_t)(n0 + rr) * 512 + kc + kk);
            }
        }
        const u64*   ab = As2 + (size_t)cb * 16 * GEMM_A_ROW + ty * 8;
        const float* bb = Bs  + (size_t)cb * 16 * GEMM_B_ROW + tx * 8;
#pragma unroll
        for (int k = 0; k < 16; k++) {
            const ulonglong2* ap = (const ulonglong2*)(ab + (size_t)k * GEMM_A_ROW);
            ulonglong2 A01 = ap[0], A23 = ap[1], A45 = ap[2], A67 = ap[3];
            const ulonglong2* bp = (const ulonglong2*)(bb + (size_t)k * GEMM_B_ROW);
            ulonglong2 Bq0 = bp[0], Bq1 = bp[1];
            u64 av[8] = {A01.x, A01.y, A23.x, A23.y, A45.x, A45.y, A67.x, A67.y};
            u64 bv[4] = {Bq0.x, Bq0.y, Bq1.x, Bq1.y};
#pragma unroll
            for (int i = 0; i < 8; i++) {
                acc2[i][0] = ffma2(av[i], bv[0], acc2[i][0]);
                acc2[i][1] = ffma2(av[i], bv[1], acc2[i][1]);
                acc2[i][2] = ffma2(av[i], bv[2], acc2[i][2]);
                acc2[i][3] = ffma2(av[i], bv[3], acc2[i][3]);
            }
        }
        if (s < 31) {
            const int nb = (s + 1) & 1;
#pragma unroll
            for (int j = 0; j < 2; j++) {
                int i  = tid + j * 256;
                int rr = i >> 2;
                int kk = (i & 3) << 2;
                u64* ad = As2 + ((size_t)nb * 16 + kk) * GEMM_A_ROW + rr;
                ad[0 * GEMM_A_ROW] = pack2(ra[j].x, ra[j].x);
                ad[1 * GEMM_A_ROW] = pack2(ra[j].y, ra[j].y);
                ad[2 * GEMM_A_ROW] = pack2(ra[j].z, ra[j].z);
                ad[3 * GEMM_A_ROW] = pack2(ra[j].w, ra[j].w);
                float* bd = Bs + ((size_t)nb * 16 + kk) * GEMM_B_ROW + rr;
                bd[0 * GEMM_B_ROW] = rb[j].x;
                bd[1 * GEMM_B_ROW] = rb[j].y;
                bd[2 * GEMM_B_ROW] = rb[j].z;
                bd[3 * GEMM_B_ROW] = rb[j].w;
            }
        }
        __syncthreads();
    }

#pragma unroll
    for (int i = 0; i < 8; i++) {
        float c0, c1, c2, c3, c4, c5, c6, c7;
        unpack2(acc2[i][0], c0, c1);
        unpack2(acc2[i][1], c2, c3);
        unpack2(acc2[i][2], c4, c5);
        unpack2(acc2[i][3], c6, c7);
        float* cp = g_xproj + (size_t)(m0 + ty * 8 + i) * 512 + n0 + tx * 8;
        *(float4*)cp       = make_float4(c0, c1, c2, c3);
        *(float4*)(cp + 4) = make_float4(c4, c5, c6, c7);
    }
}

// ============================================================================
// Kernel 2: recurrent scan. 16 clusters x 8 CTAs, 512 threads (16 warps).
// Warp w owns dims [4w,4w+4) of the CTA's 64-dim slice, all 8 batch; lanes
// split k; accumulators packed over K-PAIRS (both FFMA2 operands natural).
// h exchanged via L2 + barrier.cluster (release/acquire), refill as float4.
// ============================================================================
#define WT_FLOATS (64 * 512)                               // 128 KB
#define SCAN_SMEM ((WT_FLOATS + 8 * 512) * 4)              // 147456 B

#define RED2(OFF)                                                             \
    {                                                                         \
        const bool hi_ = (lane & (OFF)) != 0;                                 \
        _Pragma("unroll")                                                     \
        for (int i_ = 0; i_ < (OFF); i_++) {                                  \
            u64 send_ = hi_ ? acc2[i_] : acc2[i_ + (OFF)];                    \
            float sl_, sh_;                                                   \
            unpack2(send_, sl_, sh_);                                         \
            sl_ = __shfl_xor_sync(0xffffffffu, sl_, (OFF));                   \
            sh_ = __shfl_xor_sync(0xffffffffu, sh_, (OFF));                   \
            u64 keep_ = hi_ ? acc2[i_ + (OFF)] : acc2[i_];                    \
            acc2[i_] = fadd2(keep_, pack2(sl_, sh_));                         \
        }                                                                     \
    }

__global__ void __cluster_dims__(8, 1, 1) __launch_bounds__(512, 1)
rnn_scan(const float* __restrict__ Wh, const float* __restrict__ bh,
         float* __restrict__ out) {
    extern __shared__ __align__(16) float smem[];
    float* Wt = smem;               // [64][512] row-major W_h slice
    float* hb = smem + WT_FLOATS;   // [8][512]  h(t), k-contiguous per batch

    const int tid  = threadIdx.x;
    const int lane = tid & 31;
    const int w    = tid >> 5;          // warp 0..15 -> dims [4w, 4w+4)
    const int r    = blockIdx.x & 7;    // cluster rank -> dim slice
    const int g    = blockIdx.x >> 3;   // batch group

    // load W_h slice straight row-major (64 rows x 512)
    {
        const float4* ws = (const float4*)(Wh + (size_t)(r * 64) * 512);
        float4* wd = (float4*)Wt;
        for (int i = tid; i < WT_FLOATS / 4; i += 512) wd[i] = __ldg(ws + i);
    }
    // h(0) = 0
    {
        float4  z4  = make_float4(0.f, 0.f, 0.f, 0.f);
        float4* hd4 = (float4*)hb;
        for (int i = tid; i < 8 * 512 / 4; i += 512) hd4[i] = z4;
    }
    __syncthreads();

    // lane -> output (dd = lane>>3, b = lane&7); item index == lane
    const int dd      = lane >> 3;
    const int bl      = lane & 7;
    const int d_glob  = r * 64 + w * 4 + dd;
    const int b_glob  = g * 8 + bl;
    const float bias  = bh[d_glob];
    const float* xp_base = g_xproj + (size_t)b_glob * DIM + d_glob;
    const float* Ww = Wt + (size_t)(w * 4) * 512;

    // refill assignment: thread -> (b, k-octet)
    const int fb  = tid >> 6;           // batch 0..7
    const int fk0 = (tid & 63) * 8;     // k offset
    const float* fsrc0 = g_h[0] + (size_t)(g * 8 + fb) * 512 + fk0;
    const float* fsrc1 = g_h[1] + (size_t)(g * 8 + fb) * 512 + fk0;
    float* fdst = hb + fb * 512 + fk0;

    float xp = __ldg(xp_base);          // xp(0)

    for (int t = 0; t < T_STEPS; t++) {
        u64 acc2[32];
#pragma unroll
        for (int i = 0; i < 32; i++) acc2[i] = 0ull;

        // lane covers k-pairs kp = i*32 + lane  (k = 2*kp, 2*kp+1)
#pragma unroll 2
        for (int i = 0; i < 8; i++) {
            const int ko = (i * 32 + lane) * 2;
            u64 wv[4], hv[8];
#pragma unroll
            for (int d = 0; d < 4; d++)
                wv[d] = *(const u64*)(Ww + (size_t)d * 512 + ko);
#pragma unroll
            for (int b = 0; b < 8; b++)
                hv[b] = *(const u64*)(hb + (size_t)b * 512 + ko);
#pragma unroll
            for (int d = 0; d < 4; d++)
#pragma unroll
                for (int b = 0; b < 8; b++)
                    acc2[d * 8 + b] = ffma2(wv[d], hv[b], acc2[d * 8 + b]);
        }

        // butterfly: 32 packed items over 32 lanes -> lane holds item `lane`
        RED2(16) RED2(8) RED2(4) RED2(2) RED2(1)

        float zl, zh;
        unpack2(acc2[0], zl, zh);
        const float z = (zl + zh) + xp + bias;
        const float h = 1.0f / (1.0f + __expf(-z));

        if (t < T_STEPS - 1) {
            // publish own slice to L2; barrier.cluster gives release/acquire
            g_h[t & 1][(size_t)b_glob * DIM + d_glob] = h;
            asm volatile("barrier.cluster.arrive.aligned;" ::: "memory");
            // prefetch xp(t+1) off the critical path
            xp = __ldg(xp_base + (size_t)(t + 1) * BATCH * DIM);
            asm volatile("barrier.cluster.wait.aligned;"   ::: "memory");
            // refill full h(t+1) for the group (16KB, float4, L2-resident)
            {
                const float4* s4 = (const float4*)((t & 1) ? fsrc1 : fsrc0);
                float4 v0 = __ldcg(s4);
                float4 v1 = __ldcg(s4 + 1);
                *(float4*)fdst       = v0;
                *(float4*)(fdst + 4) = v1;
            }
            __syncthreads();
        } else {
            out[(size_t)b_glob * DIM + d_glob] = h;
        }
    }
}

// ============================================================================
extern "C" void kernel_launch(void* const* d_in, const int* in_sizes, int n_in,
                              void* d_out, int out_size) {
    const float* X    = (const float*)d_in[0];  // [512,128,512]
    const float* W_in = (const float*)d_in[1];  // [512,512]
    const float* W_h  = (const float*)d_in[2];  // [512,512]
    const float* b_h  = (const float*)d_in[3];  // [512]
    float* out = (float*)d_out;                 // [128,512]

    (void)in_sizes; (void)n_in; (void)out_size;

    cudaFuncSetAttribute(xproj_gemm,
                         cudaFuncAttributeMaxDynamicSharedMemorySize,
                         GEMM_SMEM);
    dim3 g1(DIM / 128, M_ROWS / 128);   // (4, 512)
    xproj_gemm<<<g1, 256, GEMM_SMEM>>>(X, W_in);

    cudaFuncSetAttribute(rnn_scan,
                         cudaFuncAttributeMaxDynamicSharedMemorySize,
                         SCAN_SMEM);
    rnn_scan<<<128, 512, SCAN_SMEM>>>(W_h, b_h, out);
}

// round 6
// speedup vs baseline: 1.8454x; 1.8454x over previous
#include <cuda_runtime.h>
#include <cstdint>

#define T_STEPS 512
#define BATCH   128
#define DIM     512
#define M_ROWS  (T_STEPS * BATCH)   // 65536

typedef unsigned long long u64;

// Scratch
__device__ float g_xproj[(size_t)T_STEPS * BATCH * DIM];  // 134 MB

// ---------------------------------------------------------------------------
// packed f32x2 helpers (FFMA2 only reachable via PTX)
// ---------------------------------------------------------------------------
__device__ __forceinline__ u64 pack2(float lo, float hi) {
    u64 r;
    asm("mov.b64 %0, {%1, %2};" : "=l"(r) : "f"(lo), "f"(hi));
    return r;
}
__device__ __forceinline__ void unpack2(u64 v, float& lo, float& hi) {
    asm("mov.b64 {%0, %1}, %2;" : "=f"(lo), "=f"(hi) : "l"(v));
}
__device__ __forceinline__ u64 ffma2(u64 a, u64 b, u64 c) {
    u64 d;
    asm("fma.rn.f32x2 %0, %1, %2, %3;" : "=l"(d) : "l"(a), "l"(b), "l"(c));
    return d;
}
__device__ __forceinline__ u64 fadd2(u64 a, u64 b) {
    u64 d;
    asm("add.rn.f32x2 %0, %1, %2;" : "=l"(d) : "l"(a), "l"(b));
    return d;
}

// ============================================================================
// Kernel 1: Xproj = X @ W_in^T. FFMA2 with PRE-DUPLICATED A pairs in SMEM.
// 128x128 tile, BK=16, 256 threads, 8x8 micro, acc packed over n-pairs.
// ============================================================================
#define GEMM_A_ROW 130   // u64 per k-row (128 + 2 pad)
#define GEMM_B_ROW 132   // floats per k-row
#define GEMM_SMEM  (2*16*GEMM_A_ROW*8 + 2*16*GEMM_B_ROW*4)   // 50176 B

__global__ void __launch_bounds__(256, 2)
xproj_gemm(const float* __restrict__ A, const float* __restrict__ W) {
    extern __shared__ __align__(16) char gsm[];
    u64*   As2 = (u64*)gsm;                                // [2][16][130] dup
    float* Bs  = (float*)(gsm + 2 * 16 * GEMM_A_ROW * 8);  // [2][16][132]

    const int tid = threadIdx.x;
    const int tx = tid & 15;
    const int ty = tid >> 4;
    const int m0 = blockIdx.y * 128;
    const int n0 = blockIdx.x * 128;

    u64 acc2[8][4];
#pragma unroll
    for (int i = 0; i < 8; i++)
#pragma unroll
        for (int j = 0; j < 4; j++) acc2[i][j] = 0ull;

    float4 ra[2], rb[2];

#pragma unroll
    for (int j = 0; j < 2; j++) {
        int i  = tid + j * 256;
        int rr = i >> 2;
        int kk = (i & 3) << 2;
        ra[j] = *(const float4*)(A + (size_t)(m0 + rr) * 512 + kk);
        rb[j] = *(const float4*)(W + (size_t)(n0 + rr) * 512 + kk);
    }
#pragma unroll
    for (int j = 0; j < 2; j++) {
        int i  = tid + j * 256;
        int rr = i >> 2;
        int kk = (i & 3) << 2;
        u64* ad = As2 + (size_t)kk * GEMM_A_ROW + rr;
        ad[0 * GEMM_A_ROW] = pack2(ra[j].x, ra[j].x);
        ad[1 * GEMM_A_ROW] = pack2(ra[j].y, ra[j].y);
        ad[2 * GEMM_A_ROW] = pack2(ra[j].z, ra[j].z);
        ad[3 * GEMM_A_ROW] = pack2(ra[j].w, ra[j].w);
        float* bd = Bs + (size_t)kk * GEMM_B_ROW + rr;
        bd[0 * GEMM_B_ROW] = rb[j].x;
        bd[1 * GEMM_B_ROW] = rb[j].y;
        bd[2 * GEMM_B_ROW] = rb[j].z;
        bd[3 * GEMM_B_ROW] = rb[j].w;
    }
    __syncthreads();

    for (int s = 0; s < 32; s++) {
        const int cb = s & 1;
        if (s < 31) {
            const int kc = (s + 1) * 16;
#pragma unroll
            for (int j = 0; j < 2; j++) {
                int i  = tid + j * 256;
                int rr = i >> 2;
                int kk = (i & 3) << 2;
                ra[j] = *(const float4*)(A + (size_t)(m0 + rr) * 512 + kc + kk);
                rb[j] = *(const float4*)(W + (size_t)(n0 + rr) * 512 + kc + kk);
            }
        }
        const u64*   ab = As2 + (size_t)cb * 16 * GEMM_A_ROW + ty * 8;
        const float* bb = Bs  + (size_t)cb * 16 * GEMM_B_ROW + tx * 8;
#pragma unroll
        for (int k = 0; k < 16; k++) {
            const ulonglong2* ap = (const ulonglong2*)(ab + (size_t)k * GEMM_A_ROW);
            ulonglong2 A01 = ap[0], A23 = ap[1], A45 = ap[2], A67 = ap[3];
            const ulonglong2* bp = (const ulonglong2*)(bb + (size_t)k * GEMM_B_ROW);
            ulonglong2 Bq0 = bp[0], Bq1 = bp[1];
            u64 av[8] = {A01.x, A01.y, A23.x, A23.y, A45.x, A45.y, A67.x, A67.y};
            u64 bv[4] = {Bq0.x, Bq0.y, Bq1.x, Bq1.y};
#pragma unroll
            for (int i = 0; i < 8; i++) {
                acc2[i][0] = ffma2(av[i], bv[0], acc2[i][0]);
                acc2[i][1] = ffma2(av[i], bv[1], acc2[i][1]);
                acc2[i][2] = ffma2(av[i], bv[2], acc2[i][2]);
                acc2[i][3] = ffma2(av[i], bv[3], acc2[i][3]);
            }
        }
        if (s < 31) {
            const int nb = (s + 1) & 1;
#pragma unroll
            for (int j = 0; j < 2; j++) {
                int i  = tid + j * 256;
                int rr = i >> 2;
                int kk = (i & 3) << 2;
                u64* ad = As2 + ((size_t)nb * 16 + kk) * GEMM_A_ROW + rr;
                ad[0 * GEMM_A_ROW] = pack2(ra[j].x, ra[j].x);
                ad[1 * GEMM_A_ROW] = pack2(ra[j].y, ra[j].y);
                ad[2 * GEMM_A_ROW] = pack2(ra[j].z, ra[j].z);
                ad[3 * GEMM_A_ROW] = pack2(ra[j].w, ra[j].w);
                float* bd = Bs + ((size_t)nb * 16 + kk) * GEMM_B_ROW + rr;
                bd[0 * GEMM_B_ROW] = rb[j].x;
                bd[1 * GEMM_B_ROW] = rb[j].y;
                bd[2 * GEMM_B_ROW] = rb[j].z;
                bd[3 * GEMM_B_ROW] = rb[j].w;
            }
        }
        __syncthreads();
    }

#pragma unroll
    for (int i = 0; i < 8; i++) {
        float c0, c1, c2, c3, c4, c5, c6, c7;
        unpack2(acc2[i][0], c0, c1);
        unpack2(acc2[i][1], c2, c3);
        unpack2(acc2[i][2], c4, c5);
        unpack2(acc2[i][3], c6, c7);
        float* cp = g_xproj + (size_t)(m0 + ty * 8 + i) * 512 + n0 + tx * 8;
        *(float4*)cp       = make_float4(c0, c1, c2, c3);
        *(float4*)(cp + 4) = make_float4(c4, c5, c6, c7);
    }
}

// ============================================================================
// Kernel 2: recurrent scan — R3 skeleton at 16 warps (512 threads).
// 16 clusters x 8 CTAs. CTA rank r owns dims [r*64, r*64+64); warp w owns
// dims [4w, 4w+4) (2 d-pair rows), all 8 batches; lanes split k (d-pair
// packed accs, 16 per lane). DSMEM push + barrier.cluster exchange (as R3).
// ============================================================================
#define HB_BUF_BYTES 16384           // 8 batch x 512 dims x 4B
#define WT2_FLOATS   (64 * 512)      // 128 KB
#define SCAN_SMEM    ((WT2_FLOATS + 2 * 8 * 512) * 4)   // 163840 B

#define RED2(OFF)                                                             \
    {                                                                         \
        const bool hi_ = (lane & (OFF)) != 0;                                 \
        _Pragma("unroll")                                                     \
        for (int i_ = 0; i_ < (OFF); i_++) {                                  \
            u64 send_ = hi_ ? acc2[i_] : acc2[i_ + (OFF)];                    \
            float sl_, sh_;                                                   \
            unpack2(send_, sl_, sh_);                                         \
            sl_ = __shfl_xor_sync(0xffffffffu, sl_, (OFF));                   \
            sh_ = __shfl_xor_sync(0xffffffffu, sh_, (OFF));                   \
            u64 keep_ = hi_ ? acc2[i_ + (OFF)] : acc2[i_];                    \
            acc2[i_] = fadd2(keep_, pack2(sl_, sh_));                         \
        }                                                                     \
    }

__global__ void __cluster_dims__(8, 1, 1) __launch_bounds__(512, 1)
rnn_scan(const float* __restrict__ Wh, const float* __restrict__ bh,
         float* __restrict__ out) {
    extern __shared__ __align__(16) float smem[];
    float* Wt = smem;                    // d-pair interleaved W_h slice
    float* hb = smem + WT2_FLOATS;       // [2][8][512] double-buffered h

    const int tid  = threadIdx.x;
    const int lane = tid & 31;
    const int w    = tid >> 5;           // warp 0..15 -> dims [4w, 4w+4)
    const int r    = blockIdx.x & 7;     // cluster rank -> dim slice
    const int g    = blockIdx.x >> 3;    // batch group

    // load W_h slice, interleaved by d-pairs:
    // Wt[p*1024 + 2k + parity] = W_h[r*64 + 2p + parity][k]
    for (int idx = tid; idx < 64 * 512 / 4; idx += 512) {
        int dl = idx >> 7;               // local dim 0..63
        int k4 = (idx & 127) << 2;       // k, step 4
        float4 v = __ldg((const float4*)(Wh + (size_t)(r * 64 + dl) * 512 + k4));
        float* wdst = Wt + (dl >> 1) * 1024 + (dl & 1);
        wdst[2 * (k4 + 0)] = v.x;
        wdst[2 * (k4 + 1)] = v.y;
        wdst[2 * (k4 + 2)] = v.z;
        wdst[2 * (k4 + 3)] = v.w;
    }
    // zero ONLY buffer 0 (buffer 1 is written remotely at t=0)
    {
        float4  z4  = make_float4(0.f, 0.f, 0.f, 0.f);
        float4* hd4 = (float4*)hb;
        for (int i = tid; i < 8 * 512 / 4; i += 512) hd4[i] = z4;
    }
    __syncthreads();

    // after reduction lane L (and L+16) holds item j = L&15:
    // j = bl*2 + dp,  output dims dglob..dglob+1
    const int lm    = lane & 15;
    const int bl    = lm >> 1;
    const int dp    = lm & 1;
    const int dglob = r * 64 + w * 4 + dp * 2;
    const int bglob = g * 8 + bl;

    const u64 bias2 = pack2(bh[dglob], bh[dglob + 1]);
    const float* xp_ptr = g_xproj + (size_t)bglob * DIM + dglob;

    // DSMEM destinations: this item's float2 slot in every rank's hb
    uint32_t hb_u32;
    {
        size_t gp = __cvta_generic_to_shared(hb);
        hb_u32 = (uint32_t)gp;
    }
    const uint32_t slot_off = (uint32_t)(bl * 2048 + dglob * 4);
    uint32_t dst[8];
#pragma unroll
    for (int rr = 0; rr < 8; rr++) {
        asm("mapa.shared::cluster.u32 %0, %1, %2;"
            : "=r"(dst[rr]) : "r"(hb_u32 + slot_off), "r"(rr));
    }

    const float* WtW = Wt + (size_t)(w * 2) * 1024;  // warp's 2 d-pair rows

    float2 xp = *(const float2*)xp_ptr;              // xp(0)

    for (int t = 0; t < T_STEPS; t++) {
        const int p = t & 1;
        const float* hbp = hb + p * 4096;            // read buffer

        u64 acc2[16];
#pragma unroll
        for (int i = 0; i < 16; i++) acc2[i] = 0ull;

        // lane covers k = ki*64 + lane*2 (+1)
#pragma unroll 2
        for (int ki = 0; ki < 8; ki++) {
            const int k = ki * 64 + lane * 2;
            ulonglong2 wq0 = *(const ulonglong2*)(WtW + 2 * k);          // dims 4w,4w+1
            ulonglong2 wq1 = *(const ulonglong2*)(WtW + 1024 + 2 * k);   // dims 4w+2,4w+3
#pragma unroll
            for (int b = 0; b < 8; b++) {
                float2 hv = *(const float2*)(hbp + b * 512 + k);
                u64 hd0 = pack2(hv.x, hv.x);
                u64 hd1 = pack2(hv.y, hv.y);
                acc2[b * 2 + 0] = ffma2(hd0, wq0.x, acc2[b * 2 + 0]);
                acc2[b * 2 + 0] = ffma2(hd1, wq0.y, acc2[b * 2 + 0]);
                acc2[b * 2 + 1] = ffma2(hd0, wq1.x, acc2[b * 2 + 1]);
                acc2[b * 2 + 1] = ffma2(hd1, wq1.y, acc2[b * 2 + 1]);
            }
        }

        // reduce 16 items over lane bits 8,4,2,1; then fold across bit 16
        RED2(8) RED2(4) RED2(2) RED2(1)
        {
            float sl, sh;
            unpack2(acc2[0], sl, sh);
            sl = __shfl_xor_sync(0xffffffffu, sl, 16);
            sh = __shfl_xor_sync(0xffffffffu, sh, 16);
            acc2[0] = fadd2(acc2[0], pack2(sl, sh));
        }

        u64 z2 = fadd2(fadd2(acc2[0], pack2(xp.x, xp.y)), bias2);
        float z0, z1;
        unpack2(z2, z0, z1);
        const float h0 = 1.0f / (1.0f + __expf(-z0));
        const float h1 = 1.0f / (1.0f + __expf(-z1));
        const u64 hh = pack2(h0, h1);

        if (t < T_STEPS - 1) {
            if (lane < 16) {
                const uint32_t boff = (uint32_t)((p ^ 1) * HB_BUF_BYTES);
#pragma unroll
                for (int rr = 0; rr < 8; rr++) {
                    asm volatile("st.shared::cluster.u64 [%0], %1;"
                                 :: "r"(dst[rr] + boff), "l"(hh) : "memory");
                }
            }
            asm volatile("barrier.cluster.arrive.aligned;" ::: "memory");
            // prefetch xp(t+1) while peers finish their pushes
            xp = __ldg((const float2*)(xp_ptr + (size_t)(t + 1) * BATCH * DIM));
            asm volatile("barrier.cluster.wait.aligned;"   ::: "memory");
        } else if (lane < 16) {
            *(float2*)(out + (size_t)bglob * DIM + dglob) = make_float2(h0, h1);
        }
    }
}

// ============================================================================
extern "C" void kernel_launch(void* const* d_in, const int* in_sizes, int n_in,
                              void* d_out, int out_size) {
    const float* X    = (const float*)d_in[0];  // [512,128,512]
    const float* W_in = (const float*)d_in[1];  // [512,512]
    const float* W_h  = (const float*)d_in[2];  // [512,512]
    const float* b_h  = (const float*)d_in[3];  // [512]
    float* out = (float*)d_out;                 // [128,512]

    (void)in_sizes; (void)n_in; (void)out_size;

    cudaFuncSetAttribute(xproj_gemm,
                         cudaFuncAttributeMaxDynamicSharedMemorySize,
                         GEMM_SMEM);
    dim3 g1(DIM / 128, M_ROWS / 128);   // (4, 512)
    xproj_gemm<<<g1, 256, GEMM_SMEM>>>(X, W_in);

    cudaFuncSetAttribute(rnn_scan,
                         cudaFuncAttributeMaxDynamicSharedMemorySize,
                         SCAN_SMEM);
    rnn_scan<<<128, 512, SCAN_SMEM>>>(W_h, b_h, out);
}